// round 4
// baseline (speedup 1.0000x reference)
#include <cuda_runtime.h>
#include <cstdint>

#define TOKENS 8192
#define HIDDEN 4096
#define INTER  11008
#define KACT   3302
#define KPAD   3328   // 52 * 64, zero-padded tail

// Scratch for the intermediate h = silu(g)*u. Static device global: no allocation.
__device__ float g_hbuf[(size_t)TOKENS * KPAD];

__device__ __forceinline__ uint32_t f2tf(float f) {
    uint32_t u;
    asm("cvt.rna.tf32.f32 %0, %1;" : "=r"(u) : "f"(f));
    return u;
}

__device__ __forceinline__ void mma8(float c[4], const uint32_t a[4], const uint32_t b[2]) {
    asm volatile(
        "mma.sync.aligned.m16n8k8.row.col.f32.tf32.tf32.f32 "
        "{%0,%1,%2,%3}, {%4,%5,%6,%7}, {%8,%9}, {%0,%1,%2,%3};\n"
        : "+f"(c[0]), "+f"(c[1]), "+f"(c[2]), "+f"(c[3])
        : "r"(a[0]), "r"(a[1]), "r"(a[2]), "r"(a[3]), "r"(b[0]), "r"(b[1]));
}

// ---------------------------------------------------------------------------
// Kernel 1: fused gate+up GEMM + silu epilogue.
//   C tile 128(tokens) x 64(k-active), K loop over HIDDEN=4096 in steps of 32.
//   8 warps (4x2), warp tile 32x32, dual accumulators (gate & up share A).
// ---------------------------------------------------------------------------
__global__ __launch_bounds__(256) void k_gateup(
    const float* __restrict__ x, const float* __restrict__ Wg,
    const float* __restrict__ Wu, const int* __restrict__ aidx)
{
    __shared__ uint32_t As [128][36];
    __shared__ uint32_t Bgs[ 64][36];
    __shared__ uint32_t Bus[ 64][36];

    const int tid = threadIdx.x;

    // Supertile raster: groups of 8 token-tiles; keeps wave working set in L2.
    const int tiles_n = KPAD / 64;          // 52
    const int GRP = 8;
    int bid   = blockIdx.x;
    int group = bid / (GRP * tiles_n);
    int rem   = bid - group * (GRP * tiles_n);
    const int bm = (group * GRP + (rem % GRP)) * 128;  // token base
    const int bn = (rem / GRP) * 64;                   // k-active base

    // Global->smem staging assignment: row lr (+32*i), 4 consecutive floats at lc.
    const int lr = tid >> 3;
    const int lc = (tid & 7) * 4;

    const float* aptr[4];
    const float* gptr[2];
    const float* uptr[2];
#pragma unroll
    for (int i = 0; i < 4; ++i)
        aptr[i] = x + (size_t)(bm + lr + 32 * i) * HIDDEN + lc;
#pragma unroll
    for (int i = 0; i < 2; ++i) {
        int n = bn + lr + 32 * i;
        if (n > KACT - 1) n = KACT - 1;                // clamp pad rows (masked later)
        int row = __ldg(&aidx[n]);
        gptr[i] = Wg + (size_t)row * HIDDEN + lc;
        uptr[i] = Wu + (size_t)row * HIDDEN + lc;
    }

    const int warp = tid >> 5, lane = tid & 31;
    const int wm = (warp & 3) * 32;
    const int wn = (warp >> 2) * 32;
    const int lr4 = lane >> 2, lc4 = lane & 3;

    float accg[2][4][4] = {};
    float accu[2][4][4] = {};

    float4 ra[4], rg[2], ru[2];
#pragma unroll
    for (int i = 0; i < 4; ++i) ra[i] = *(const float4*)(aptr[i]);
#pragma unroll
    for (int i = 0; i < 2; ++i) { rg[i] = *(const float4*)(gptr[i]); ru[i] = *(const float4*)(uptr[i]); }

    const int KT = HIDDEN / 32;   // 128
    for (int kt = 0; kt < KT; ++kt) {
#pragma unroll
        for (int i = 0; i < 4; ++i) {
            uint4 v = make_uint4(f2tf(ra[i].x), f2tf(ra[i].y), f2tf(ra[i].z), f2tf(ra[i].w));
            *(uint4*)&As[lr + 32 * i][lc] = v;
        }
#pragma unroll
        for (int i = 0; i < 2; ++i) {
            uint4 v = make_uint4(f2tf(rg[i].x), f2tf(rg[i].y), f2tf(rg[i].z), f2tf(rg[i].w));
            *(uint4*)&Bgs[lr + 32 * i][lc] = v;
            uint4 w = make_uint4(f2tf(ru[i].x), f2tf(ru[i].y), f2tf(ru[i].z), f2tf(ru[i].w));
            *(uint4*)&Bus[lr + 32 * i][lc] = w;
        }
        __syncthreads();

        if (kt + 1 < KT) {                 // prefetch next tile: overlaps with MMA below
            const int off = (kt + 1) * 32;
#pragma unroll
            for (int i = 0; i < 4; ++i) ra[i] = *(const float4*)(aptr[i] + off);
#pragma unroll
            for (int i = 0; i < 2; ++i) { rg[i] = *(const float4*)(gptr[i] + off); ru[i] = *(const float4*)(uptr[i] + off); }
        }

#pragma unroll
        for (int kk = 0; kk < 4; ++kk) {
            const int kb = kk * 8;
            uint32_t af[2][4];
#pragma unroll
            for (int i = 0; i < 2; ++i) {
                int r = wm + i * 16 + lr4;
                af[i][0] = As[r    ][kb + lc4];
                af[i][1] = As[r + 8][kb + lc4];
                af[i][2] = As[r    ][kb + lc4 + 4];
                af[i][3] = As[r + 8][kb + lc4 + 4];
            }
            uint32_t bgf[4][2], buf2[4][2];
#pragma unroll
            for (int j = 0; j < 4; ++j) {
                int n = wn + j * 8 + lr4;
                bgf[j][0]  = Bgs[n][kb + lc4];
                bgf[j][1]  = Bgs[n][kb + lc4 + 4];
                buf2[j][0] = Bus[n][kb + lc4];
                buf2[j][1] = Bus[n][kb + lc4 + 4];
            }
#pragma unroll
            for (int i = 0; i < 2; ++i)
#pragma unroll
                for (int j = 0; j < 4; ++j) {
                    mma8(accg[i][j], af[i], bgf[j]);
                    mma8(accu[i][j], af[i], buf2[j]);
                }
        }
        __syncthreads();
    }

    // Epilogue: h = silu(g) * u ; zero the pad columns so K2 can run K=KPAD clean.
#pragma unroll
    for (int i = 0; i < 2; ++i) {
#pragma unroll
        for (int j = 0; j < 4; ++j) {
            int c0 = bn + wn + j * 8 + 2 * lc4;       // even; KACT even -> pair-mask ok
            bool valid = (c0 < KACT);
#pragma unroll
            for (int half = 0; half < 2; ++half) {
                int r = bm + wm + i * 16 + lr4 + half * 8;
                float g0 = accg[i][j][half * 2], g1 = accg[i][j][half * 2 + 1];
                float u0 = accu[i][j][half * 2], u1 = accu[i][j][half * 2 + 1];
                float h0 = valid ? (g0 * u0 / (1.0f + __expf(-g0))) : 0.0f;
                float h1 = valid ? (g1 * u1 / (1.0f + __expf(-g1))) : 0.0f;
                *(float2*)&g_hbuf[(size_t)r * KPAD + c0] = make_float2(h0, h1);
            }
        }
    }
}

// ---------------------------------------------------------------------------
// Kernel 2: out = h @ Wd_active^T.
//   C tile 128(tokens) x 64(hidden), K loop over KPAD=3328 in steps of 32.
//   B gathered via active_idx (contiguous in practice -> coalesced).
// ---------------------------------------------------------------------------
__global__ __launch_bounds__(256) void k_down(
    const float* __restrict__ Wd, const int* __restrict__ aidx, float* __restrict__ out)
{
    __shared__ uint32_t As[128][36];
    __shared__ uint32_t Bs[ 64][36];

    const int tid = threadIdx.x;

    const int tiles_n = HIDDEN / 64;        // 64
    const int GRP = 8;
    int bid   = blockIdx.x;
    int group = bid / (GRP * tiles_n);
    int rem   = bid - group * (GRP * tiles_n);
    const int bm = (group * GRP + (rem % GRP)) * 128;  // token base
    const int bn = (rem / GRP) * 64;                   // hidden-out base

    const int lr = tid >> 3;
    const int lc = (tid & 7) * 4;

    const float* aptr[4];
#pragma unroll
    for (int i = 0; i < 4; ++i)
        aptr[i] = g_hbuf + (size_t)(bm + lr + 32 * i) * KPAD + lc;

    // B gather: each thread owns one k (= tid&31) and 8 n-rows (tid>>5 + 8*i).
    const int bk_lane = tid & 31;
    const int nrow    = tid >> 5;

    const int warp = tid >> 5, lane = tid & 31;
    const int wm = (warp & 3) * 32;
    const int wn = (warp >> 2) * 32;
    const int lr4 = lane >> 2, lc4 = lane & 3;

    float acc[2][4][4] = {};

    float4 ra[4];
    float  rb[8];
    {
        int kg = bk_lane; if (kg > KACT - 1) kg = KACT - 1;  // pad cols: h==0 anyway
        int col = __ldg(&aidx[kg]);
#pragma unroll
        for (int i = 0; i < 4; ++i) ra[i] = *(const float4*)(aptr[i]);
#pragma unroll
        for (int i = 0; i < 8; ++i)
            rb[i] = __ldg(&Wd[(size_t)(bn + nrow + 8 * i) * INTER + col]);
    }

    const int KT = KPAD / 32;   // 104
    for (int kt = 0; kt < KT; ++kt) {
#pragma unroll
        for (int i = 0; i < 4; ++i) {
            uint4 v = make_uint4(f2tf(ra[i].x), f2tf(ra[i].y), f2tf(ra[i].z), f2tf(ra[i].w));
            *(uint4*)&As[lr + 32 * i][lc] = v;
        }
#pragma unroll
        for (int i = 0; i < 8; ++i)
            Bs[nrow + 8 * i][bk_lane] = f2tf(rb[i]);
        __syncthreads();

        if (kt + 1 < KT) {
            const int off = (kt + 1) * 32;
            int kg = off + bk_lane; if (kg > KACT - 1) kg = KACT - 1;
            int col = __ldg(&aidx[kg]);
#pragma unroll
            for (int i = 0; i < 4; ++i) ra[i] = *(const float4*)(aptr[i] + off);
#pragma unroll
            for (int i = 0; i < 8; ++i)
                rb[i] = __ldg(&Wd[(size_t)(bn + nrow + 8 * i) * INTER + col]);
        }

#pragma unroll
        for (int kk = 0; kk < 4; ++kk) {
            const int kb = kk * 8;
            uint32_t af[2][4], bf[4][2];
#pragma unroll
            for (int i = 0; i < 2; ++i) {
                int r = wm + i * 16 + lr4;
                af[i][0] = As[r    ][kb + lc4];
                af[i][1] = As[r + 8][kb + lc4];
                af[i][2] = As[r    ][kb + lc4 + 4];
                af[i][3] = As[r + 8][kb + lc4 + 4];
            }
#pragma unroll
            for (int j = 0; j < 4; ++j) {
                int n = wn + j * 8 + lr4;
                bf[j][0] = Bs[n][kb + lc4];
                bf[j][1] = Bs[n][kb + lc4 + 4];
            }
#pragma unroll
            for (int i = 0; i < 2; ++i)
#pragma unroll
                for (int j = 0; j < 4; ++j)
                    mma8(acc[i][j], af[i], bf[j]);
        }
        __syncthreads();
    }

#pragma unroll
    for (int i = 0; i < 2; ++i)
#pragma unroll
        for (int j = 0; j < 4; ++j) {
            int c0 = bn + wn + j * 8 + 2 * lc4;
#pragma unroll
            for (int half = 0; half < 2; ++half) {
                int r = bm + wm + i * 16 + lr4 + half * 8;
                *(float2*)&out[(size_t)r * HIDDEN + c0] =
                    make_float2(acc[i][j][half * 2], acc[i][j][half * 2 + 1]);
            }
        }
}

// ---------------------------------------------------------------------------
// Inputs (metadata order): x[f32 8192x4096], W_gate[f32 11008x4096],
// W_up[f32 11008x4096], W_down[f32 4096x11008], active_idx[i32 3302].
// Output: f32 8192x4096.
// ---------------------------------------------------------------------------
extern "C" void kernel_launch(void* const* d_in, const int* in_sizes, int n_in,
                              void* d_out, int out_size)
{
    const float* x    = (const float*)d_in[0];
    const float* Wg   = (const float*)d_in[1];
    const float* Wu   = (const float*)d_in[2];
    const float* Wd   = (const float*)d_in[3];
    const int*   aidx = (const int*)  d_in[4];
    float*       out  = (float*)d_out;

    dim3 blk(256);
    dim3 g1((TOKENS / 128) * (KPAD / 64));      // 64 * 52 = 3328 blocks
    k_gateup<<<g1, blk>>>(x, Wg, Wu, aidx);

    dim3 g2((TOKENS / 128) * (HIDDEN / 64));    // 64 * 64 = 4096 blocks
    k_down<<<g2, blk>>>(Wd, aidx, out);
}

// round 9
// speedup vs baseline: 1.3327x; 1.3327x over previous
#include <cuda_runtime.h>
#include <cstdint>

#define TOKENS 8192
#define HIDDEN 4096
#define INTER  11008
#define KACT   3302
#define KPAD   3328   // 26 * 128, zero-padded tail

// ---------------------------------------------------------------------------
// Static device scratch (no allocations allowed). All operands pre-converted
// to tf32 bit patterns, gathered/packed, pads zero-filled.
// ---------------------------------------------------------------------------
__device__ uint32_t g_xtf [(size_t)TOKENS * HIDDEN];   // x, tf32
__device__ uint32_t g_wgtf[(size_t)KPAD   * HIDDEN];   // W_gate[aidx], packed, pad rows = 0
__device__ uint32_t g_wutf[(size_t)KPAD   * HIDDEN];   // W_up[aidx]
__device__ uint32_t g_wdtf[(size_t)HIDDEN * KPAD];     // W_down[:, aidx], packed, pad cols = 0
__device__ uint32_t g_htf [(size_t)TOKENS * KPAD];     // h = silu(g)*u, tf32

__device__ __forceinline__ uint32_t f2tf(float f) {
    uint32_t u;
    asm("cvt.rna.tf32.f32 %0, %1;" : "=r"(u) : "f"(f));
    return u;
}

__device__ __forceinline__ void mma8(float c[4], const uint32_t a[4], const uint32_t b[2]) {
    asm volatile(
        "mma.sync.aligned.m16n8k8.row.col.f32.tf32.tf32.f32 "
        "{%0,%1,%2,%3}, {%4,%5,%6,%7}, {%8,%9}, {%0,%1,%2,%3};\n"
        : "+f"(c[0]), "+f"(c[1]), "+f"(c[2]), "+f"(c[3])
        : "r"(a[0]), "r"(a[1]), "r"(a[2]), "r"(a[3]), "r"(b[0]), "r"(b[1]));
}

__device__ __forceinline__ void cp16(uint32_t smem_addr, const void* gptr) {
    asm volatile("cp.async.cg.shared.global [%0], [%1], 16;\n"
                 :: "r"(smem_addr), "l"(gptr));
}
#define CP_COMMIT() asm volatile("cp.async.commit_group;\n")
#define CP_WAIT1()  asm volatile("cp.async.wait_group 1;\n")

// ---------------------------------------------------------------------------
// Prep kernels: convert + gather + pad once per call (bandwidth-bound, ~100us)
// ---------------------------------------------------------------------------
__global__ __launch_bounds__(256) void k_cvt_x(const float* __restrict__ x) {
    size_t i = ((size_t)blockIdx.x * 256 + threadIdx.x) * 4;
    float4 v = *(const float4*)(x + i);
    *(uint4*)(g_xtf + i) = make_uint4(f2tf(v.x), f2tf(v.y), f2tf(v.z), f2tf(v.w));
}

__global__ __launch_bounds__(256) void k_prep_gu(
    const float* __restrict__ Wg, const float* __restrict__ Wu, const int* __restrict__ aidx)
{
    int r = blockIdx.x;                          // 0..KPAD-1
    uint32_t* dg = g_wgtf + (size_t)r * HIDDEN;
    uint32_t* du = g_wutf + (size_t)r * HIDDEN;
    if (r < KACT) {
        int src = __ldg(&aidx[r]);
        const float* sg = Wg + (size_t)src * HIDDEN;
        const float* su = Wu + (size_t)src * HIDDEN;
        for (int c = threadIdx.x * 4; c < HIDDEN; c += 1024) {
            float4 g = *(const float4*)(sg + c);
            float4 u = *(const float4*)(su + c);
            *(uint4*)(dg + c) = make_uint4(f2tf(g.x), f2tf(g.y), f2tf(g.z), f2tf(g.w));
            *(uint4*)(du + c) = make_uint4(f2tf(u.x), f2tf(u.y), f2tf(u.z), f2tf(u.w));
        }
    } else {
        for (int c = threadIdx.x * 4; c < HIDDEN; c += 1024) {
            *(uint4*)(dg + c) = make_uint4(0, 0, 0, 0);
            *(uint4*)(du + c) = make_uint4(0, 0, 0, 0);
        }
    }
}

__global__ __launch_bounds__(256) void k_prep_wd(
    const float* __restrict__ Wd, const int* __restrict__ aidx)
{
    int n = blockIdx.x;                          // 0..HIDDEN-1
    uint32_t* dst = g_wdtf + (size_t)n * KPAD;
    const float* src = Wd + (size_t)n * INTER;
    for (int k = threadIdx.x; k < KPAD; k += 256)
        dst[k] = (k < KACT) ? f2tf(__ldg(&src[__ldg(&aidx[k])])) : 0u;
}

// ---------------------------------------------------------------------------
// Kernel 1: g/u GEMM + silu epilogue. CTA tile 128(M tokens) x 128(N k-act),
// K step 32, double-buffered cp.async. 8 warps (2x4), warp tile 64x32 DUAL
// (gate + up share the A fragments). Writes h as tf32 bits (pads are 0).
// smem: [As0 As1 Bg0 Bg1 Bu0 Bu1], each 128x36 words = 110,592 B total.
// ---------------------------------------------------------------------------
__global__ __launch_bounds__(256, 1) void k_gateup() {
    extern __shared__ uint32_t sm[];
    const int tid = threadIdx.x;

    int bid   = blockIdx.x;                     // 64 m-tiles x 26 n-tiles, GRP=8
    int group = bid / (8 * 26);
    int rem   = bid - group * (8 * 26);
    const int bm = (group * 8 + (rem & 7)) * 128;
    const int bn = (rem >> 3) * 128;

    const int arow = tid >> 3;                  // 0..31
    const int acol = (tid & 7) * 4;             // word col 0,4,..,28

    const uint32_t sbase = (uint32_t)__cvta_generic_to_shared(sm);
    const uint32_t woff  = (uint32_t)(arow * 36 + acol) * 4;  // byte off within tile

    const uint32_t* xsrc = g_xtf  + (size_t)(bm + arow) * HIDDEN + acol;
    const uint32_t* gsrc = g_wgtf + (size_t)(bn + arow) * HIDDEN + acol;
    const uint32_t* usrc = g_wutf + (size_t)(bn + arow) * HIDDEN + acol;

    auto stage = [&](int s, int kt) {
        const int gk = kt * 32;
        uint32_t a_s = sbase + (uint32_t)(s * 4608) * 4 + woff;
        uint32_t g_s = sbase + (uint32_t)((2 + s) * 4608) * 4 + woff;
        uint32_t u_s = sbase + (uint32_t)((4 + s) * 4608) * 4 + woff;
#pragma unroll
        for (int i = 0; i < 4; ++i) {
            cp16(a_s + i * (32 * 36 * 4), xsrc + (size_t)(32 * i) * HIDDEN + gk);
            cp16(g_s + i * (32 * 36 * 4), gsrc + (size_t)(32 * i) * HIDDEN + gk);
            cp16(u_s + i * (32 * 36 * 4), usrc + (size_t)(32 * i) * HIDDEN + gk);
        }
    };

    const int warp = tid >> 5, lane = tid & 31;
    const int wm = (warp & 1) * 64;
    const int wn = (warp >> 1) * 32;
    const int lr4 = lane >> 2, lc4 = lane & 3;

    float accg[4][4][4] = {};
    float accu[4][4][4] = {};

    const int KT = HIDDEN / 32;                 // 128
    stage(0, 0);
    CP_COMMIT();

    for (int kt = 0; kt < KT; ++kt) {
        const int cur = kt & 1;
        if (kt + 1 < KT) stage(cur ^ 1, kt + 1);
        CP_COMMIT();
        CP_WAIT1();
        __syncthreads();

        const uint32_t* As = sm + cur * 4608;
        const uint32_t* Bg = sm + (2 + cur) * 4608;
        const uint32_t* Bu = sm + (4 + cur) * 4608;
#pragma unroll
        for (int kk = 0; kk < 4; ++kk) {
            const int kb = kk * 8;
            uint32_t af[4][4];
#pragma unroll
            for (int i = 0; i < 4; ++i) {
                int r = wm + i * 16 + lr4;
                af[i][0] = As[r * 36 + kb + lc4];
                af[i][1] = As[(r + 8) * 36 + kb + lc4];
                af[i][2] = As[r * 36 + kb + lc4 + 4];
                af[i][3] = As[(r + 8) * 36 + kb + lc4 + 4];
            }
            uint32_t bg[4][2], bu[4][2];
#pragma unroll
            for (int j = 0; j < 4; ++j) {
                int n = wn + j * 8 + lr4;
                bg[j][0] = Bg[n * 36 + kb + lc4];
                bg[j][1] = Bg[n * 36 + kb + lc4 + 4];
                bu[j][0] = Bu[n * 36 + kb + lc4];
                bu[j][1] = Bu[n * 36 + kb + lc4 + 4];
            }
#pragma unroll
            for (int i = 0; i < 4; ++i)
#pragma unroll
                for (int j = 0; j < 4; ++j) {
                    mma8(accg[i][j], af[i], bg[j]);
                    mma8(accu[i][j], af[i], bu[j]);
                }
        }
        __syncthreads();
    }

    // Epilogue: h = silu(g)*u, stored as tf32 bits. Pad cols are exactly 0.
#pragma unroll
    for (int i = 0; i < 4; ++i)
#pragma unroll
        for (int j = 0; j < 4; ++j) {
            int c0 = bn + wn + j * 8 + 2 * lc4;
#pragma unroll
            for (int half = 0; half < 2; ++half) {
                int r = bm + wm + i * 16 + lr4 + half * 8;
                float g0 = accg[i][j][half * 2], g1 = accg[i][j][half * 2 + 1];
                float u0 = accu[i][j][half * 2], u1 = accu[i][j][half * 2 + 1];
                float h0 = g0 * u0 / (1.0f + __expf(-g0));
                float h1 = g1 * u1 / (1.0f + __expf(-g1));
                *(uint2*)(g_htf + (size_t)r * KPAD + c0) = make_uint2(f2tf(h0), f2tf(h1));
            }
        }
}

// ---------------------------------------------------------------------------
// Kernel 2: out = h @ Wd_packed^T. CTA tile 128(M) x 256(N hidden), K step 32
// over KPAD. 8 warps (2x4), warp tile 64x64. Double-buffered cp.async.
// smem: [As0 As1 | Bs0 Bs1], As 128x36, Bs 256x36 words = 110,592 B total.
// ---------------------------------------------------------------------------
__global__ __launch_bounds__(256, 1) void k_down(float* __restrict__ out) {
    extern __shared__ uint32_t sm[];
    const int tid = threadIdx.x;

    int bid   = blockIdx.x;                     // 64 m-tiles x 16 n-tiles, GRP=8
    int group = bid / (8 * 16);
    int rem   = bid - group * (8 * 16);
    const int bm = (group * 8 + (rem & 7)) * 128;
    const int bn = (rem >> 3) * 256;

    const int arow = tid >> 3;
    const int acol = (tid & 7) * 4;

    const uint32_t sbase = (uint32_t)__cvta_generic_to_shared(sm);
    const uint32_t woff  = (uint32_t)(arow * 36 + acol) * 4;

    const uint32_t* asrc = g_htf  + (size_t)(bm + arow) * KPAD + acol;
    const uint32_t* bsrc = g_wdtf + (size_t)(bn + arow) * KPAD + acol;

    auto stage = [&](int s, int kt) {
        const int gk = kt * 32;
        uint32_t a_s = sbase + (uint32_t)(s * 4608) * 4 + woff;
        uint32_t b_s = sbase + (uint32_t)(9216 + s * 9216) * 4 + woff;
#pragma unroll
        for (int i = 0; i < 4; ++i)
            cp16(a_s + i * (32 * 36 * 4), asrc + (size_t)(32 * i) * KPAD + gk);
#pragma unroll
        for (int i = 0; i < 8; ++i)
            cp16(b_s + i * (32 * 36 * 4), bsrc + (size_t)(32 * i) * KPAD + gk);
    };

    const int warp = tid >> 5, lane = tid & 31;
    const int wm = (warp & 1) * 64;
    const int wn = (warp >> 1) * 64;
    const int lr4 = lane >> 2, lc4 = lane & 3;

    float acc[4][8][4] = {};

    const int KT = KPAD / 32;                   // 104
    stage(0, 0);
    CP_COMMIT();

    for (int kt = 0; kt < KT; ++kt) {
        const int cur = kt & 1;
        if (kt + 1 < KT) stage(cur ^ 1, kt + 1);
        CP_COMMIT();
        CP_WAIT1();
        __syncthreads();

        const uint32_t* As = sm + cur * 4608;
        const uint32_t* Bs = sm + 9216 + cur * 9216;
#pragma unroll
        for (int kk = 0; kk < 4; ++kk) {
            const int kb = kk * 8;
            uint32_t af[4][4];
#pragma unroll
            for (int i = 0; i < 4; ++i) {
                int r = wm + i * 16 + lr4;
                af[i][0] = As[r * 36 + kb + lc4];
                af[i][1] = As[(r + 8) * 36 + kb + lc4];
                af[i][2] = As[r * 36 + kb + lc4 + 4];
                af[i][3] = As[(r + 8) * 36 + kb + lc4 + 4];
            }
            uint32_t bf[8][2];
#pragma unroll
            for (int j = 0; j < 8; ++j) {
                int n = wn + j * 8 + lr4;
                bf[j][0] = Bs[n * 36 + kb + lc4];
                bf[j][1] = Bs[n * 36 + kb + lc4 + 4];
            }
#pragma unroll
            for (int i = 0; i < 4; ++i)
#pragma unroll
                for (int j = 0; j < 8; ++j)
                    mma8(acc[i][j], af[i], bf[j]);
        }
        __syncthreads();
    }

#pragma unroll
    for (int i = 0; i < 4; ++i)
#pragma unroll
        for (int j = 0; j < 8; ++j) {
            int c0 = bn + wn + j * 8 + 2 * lc4;
#pragma unroll
            for (int half = 0; half < 2; ++half) {
                int r = bm + wm + i * 16 + lr4 + half * 8;
                *(float2*)(out + (size_t)r * HIDDEN + c0) =
                    make_float2(acc[i][j][half * 2], acc[i][j][half * 2 + 1]);
            }
        }
}

// ---------------------------------------------------------------------------
// Inputs: x[f32 8192x4096], W_gate[f32 11008x4096], W_up[f32 11008x4096],
// W_down[f32 4096x11008], active_idx[i32 3302]. Output f32 8192x4096.
// ---------------------------------------------------------------------------
extern "C" void kernel_launch(void* const* d_in, const int* in_sizes, int n_in,
                              void* d_out, int out_size)
{
    const float* x    = (const float*)d_in[0];
    const float* Wg   = (const float*)d_in[1];
    const float* Wu   = (const float*)d_in[2];
    const float* Wd   = (const float*)d_in[3];
    const int*   aidx = (const int*)  d_in[4];
    float*       out  = (float*)d_out;

    const int SMEM = 110592;  // 27648 words * 4B for both GEMM kernels
    cudaFuncSetAttribute(k_gateup, cudaFuncAttributeMaxDynamicSharedMemorySize, SMEM);
    cudaFuncSetAttribute(k_down,   cudaFuncAttributeMaxDynamicSharedMemorySize, SMEM);

    k_cvt_x  <<<(TOKENS * HIDDEN) / 1024, 256>>>(x);
    k_prep_gu<<<KPAD,   256>>>(Wg, Wu, aidx);
    k_prep_wd<<<HIDDEN, 256>>>(Wd, aidx);

    k_gateup<<<(TOKENS / 128) * (KPAD / 128),  256, SMEM>>>();       // 64*26 = 1664
    k_down  <<<(TOKENS / 128) * (HIDDEN / 256), 256, SMEM>>>(out);   // 64*16 = 1024
}